// round 13
// baseline (speedup 1.0000x reference)
#include <cuda_runtime.h>
#include <cstdint>

// convection_vectors: (N_NODES, 3) float32      -> d_in[0]
// mesh_elements:      (E, 4)       int32        -> d_in[1]
// inv_matrices:       (E, 4, 4)    float32      -> d_in[2]
// out:                (E, 4, 3)    float32      -> d_out
//
// out[e,i,c] = sum_j inv[e,i,j] * conv[mesh[e,j], c]

#define MAX_NODES 400000

// Padded gather table: (N, 4) so each vertex is one aligned 16B load. 6.4 MB -> L2-resident.
__device__ float4 g_conv4[MAX_NODES];

__global__ void __launch_bounds__(128)
pad_conv_kernel(const float* __restrict__ conv, int n)
{
    int i = blockIdx.x * blockDim.x + threadIdx.x;
    if (i >= n) return;
    long b = (long)i * 3;
    g_conv4[i] = make_float4(conv[b], conv[b + 1], conv[b + 2], 0.0f);
}

__device__ __forceinline__ uint32_t smem_u32(const void* p)
{
    uint32_t a;
    asm("{ .reg .u64 t; cvta.to.shared.u64 t, %1; cvt.u32.u64 %0, t; }" : "=r"(a) : "l"(p));
    return a;
}

// R7 winner, unchanged: one thread per (element,row) unit; each CTA processes
// TWO consecutive 256-row tiles, double-buffered smem staging (conflict-free
// stride-3 STS) + pipelined 1D TMA bulk stores; single drain at CTA end.
__global__ void __launch_bounds__(256)
fem_row_tma2_kernel(const int4*   __restrict__ elems,
                    const float4* __restrict__ inv,
                    float*        __restrict__ out,
                    int total_rows)   // 4*E
{
    __shared__ __align__(16) float s_out[2][256 * 3];   // 2 x 3 KB tiles

    const int tile_rows = 256;

#pragma unroll
    for (int it = 0; it < 2; it++) {
        int tile_base = (blockIdx.x * 2 + it) * tile_rows;
        int t = tile_base + threadIdx.x;
        bool full_tile = (tile_base + tile_rows <= total_rows);

        if (t < total_rows) {
            int4 idx = __ldcs(&elems[t >> 2]);
            float4 m = __ldcs(&inv[t]);

            float4 v0 = g_conv4[idx.x];
            float4 v1 = g_conv4[idx.y];
            float4 v2 = g_conv4[idx.z];
            float4 v3 = g_conv4[idx.w];

            float r0 = fmaf(m.x, v0.x, fmaf(m.y, v1.x, fmaf(m.z, v2.x, m.w * v3.x)));
            float r1 = fmaf(m.x, v0.y, fmaf(m.y, v1.y, fmaf(m.z, v2.y, m.w * v3.y)));
            float r2 = fmaf(m.x, v0.z, fmaf(m.y, v1.z, fmaf(m.z, v2.z, m.w * v3.z)));

            if (full_tile) {
                // stride-3 word addresses: gcd(3,32)=1 -> conflict-free
                int w = threadIdx.x * 3;
                s_out[it][w + 0] = r0;
                s_out[it][w + 1] = r1;
                s_out[it][w + 2] = r2;
            } else {
                float* o = out + (long)t * 3;
                __stcs(o + 0, r0);
                __stcs(o + 1, r1);
                __stcs(o + 2, r2);
            }
        }

        if (full_tile) {
            asm volatile("fence.proxy.async.shared::cta;" ::: "memory");
            __syncthreads();
            if (threadIdx.x == 0) {
                uint32_t saddr = smem_u32(s_out[it]);
                float* gptr = out + (long)tile_base * 3;   // 3072B-aligned chunk
                asm volatile(
                    "cp.async.bulk.global.shared::cta.bulk_group [%0], [%1], %2;"
                    :: "l"(gptr), "r"(saddr), "r"(tile_rows * 3 * 4) : "memory");
                asm volatile("cp.async.bulk.commit_group;" ::: "memory");
            }
        }
    }

    // Single drain at CTA end (covers both buffers).
    if (threadIdx.x == 0)
        asm volatile("cp.async.bulk.wait_group 0;" ::: "memory");
}

extern "C" void kernel_launch(void* const* d_in, const int* in_sizes, int n_in,
                              void* d_out, int out_size)
{
    const float* conv  = (const float*)d_in[0];
    const int4*  elems = (const int4*)d_in[1];
    const float4* inv  = (const float4*)d_in[2];
    float* out = (float*)d_out;

    int n_nodes = in_sizes[0] / 3;
    int E = in_sizes[1] / 4;
    int total_rows = 4 * E;

    // Maximize L1 cache for the main kernel (we use only 6 KB smem):
    // carveout hint 0% shared -> largest L1 for gather lines + streaming.
    static bool attr_set = false;
    if (!attr_set) {
        cudaFuncSetAttribute(fem_row_tma2_kernel,
                             cudaFuncAttributePreferredSharedMemoryCarveout, 0);
        cudaFuncSetAttribute(pad_conv_kernel,
                             cudaFuncAttributePreferredSharedMemoryCarveout, 0);
        attr_set = true;
    }

    pad_conv_kernel<<<(n_nodes + 127) / 128, 128>>>(conv, n_nodes);

    int rows_per_cta = 512;   // 2 tiles x 256
    int grid = (total_rows + rows_per_cta - 1) / rows_per_cta;
    fem_row_tma2_kernel<<<grid, 256>>>(elems, inv, out, total_rows);
}

// round 14
// speedup vs baseline: 3.7290x; 3.7290x over previous
#include <cuda_runtime.h>
#include <cstdint>

// convection_vectors: (N_NODES, 3) float32      -> d_in[0]
// mesh_elements:      (E, 4)       int32        -> d_in[1]
// inv_matrices:       (E, 4, 4)    float32      -> d_in[2]
// out:                (E, 4, 3)    float32      -> d_out
//
// out[e,i,c] = sum_j inv[e,i,j] * conv[mesh[e,j], c]

#define MAX_NODES 400000

// Padded gather table: (N, 4) so each vertex is one aligned 16B load. 6.4 MB -> L2-resident.
__device__ float4 g_conv4[MAX_NODES];

__global__ void __launch_bounds__(128)
pad_conv_kernel(const float* __restrict__ conv, int n)
{
    int i = blockIdx.x * blockDim.x + threadIdx.x;
    if (i >= n) return;
    long b = (long)i * 3;
    g_conv4[i] = make_float4(conv[b], conv[b + 1], conv[b + 2], 0.0f);
}

__device__ __forceinline__ uint32_t smem_u32(const void* p)
{
    uint32_t a;
    asm("{ .reg .u64 t; cvta.to.shared.u64 t, %1; cvt.u32.u64 %0, t; }" : "=r"(a) : "l"(p));
    return a;
}

// R7 winner (verified best): one thread per (element,row) unit; each CTA
// processes TWO consecutive 256-row tiles, double-buffered smem staging
// (conflict-free stride-3 STS) + pipelined 1D TMA bulk stores; single drain
// at CTA end so tile1's compute overlaps tile0's TMA drain.
__global__ void __launch_bounds__(256)
fem_row_tma2_kernel(const int4*   __restrict__ elems,
                    const float4* __restrict__ inv,
                    float*        __restrict__ out,
                    int total_rows)   // 4*E
{
    __shared__ __align__(16) float s_out[2][256 * 3];   // 2 x 3 KB tiles

    const int tile_rows = 256;

#pragma unroll
    for (int it = 0; it < 2; it++) {
        int tile_base = (blockIdx.x * 2 + it) * tile_rows;
        int t = tile_base + threadIdx.x;
        bool full_tile = (tile_base + tile_rows <= total_rows);

        if (t < total_rows) {
            int4 idx = __ldcs(&elems[t >> 2]);
            float4 m = __ldcs(&inv[t]);

            float4 v0 = g_conv4[idx.x];
            float4 v1 = g_conv4[idx.y];
            float4 v2 = g_conv4[idx.z];
            float4 v3 = g_conv4[idx.w];

            float r0 = fmaf(m.x, v0.x, fmaf(m.y, v1.x, fmaf(m.z, v2.x, m.w * v3.x)));
            float r1 = fmaf(m.x, v0.y, fmaf(m.y, v1.y, fmaf(m.z, v2.y, m.w * v3.y)));
            float r2 = fmaf(m.x, v0.z, fmaf(m.y, v1.z, fmaf(m.z, v2.z, m.w * v3.z)));

            if (full_tile) {
                // stride-3 word addresses: gcd(3,32)=1 -> conflict-free
                int w = threadIdx.x * 3;
                s_out[it][w + 0] = r0;
                s_out[it][w + 1] = r1;
                s_out[it][w + 2] = r2;
            } else {
                float* o = out + (long)t * 3;
                __stcs(o + 0, r0);
                __stcs(o + 1, r1);
                __stcs(o + 2, r2);
            }
        }

        if (full_tile) {
            asm volatile("fence.proxy.async.shared::cta;" ::: "memory");
            __syncthreads();
            if (threadIdx.x == 0) {
                uint32_t saddr = smem_u32(s_out[it]);
                float* gptr = out + (long)tile_base * 3;   // 3072B-aligned chunk
                asm volatile(
                    "cp.async.bulk.global.shared::cta.bulk_group [%0], [%1], %2;"
                    :: "l"(gptr), "r"(saddr), "r"(tile_rows * 3 * 4) : "memory");
                asm volatile("cp.async.bulk.commit_group;" ::: "memory");
            }
        }
    }

    // Single drain at CTA end (covers both buffers).
    if (threadIdx.x == 0)
        asm volatile("cp.async.bulk.wait_group 0;" ::: "memory");
}

extern "C" void kernel_launch(void* const* d_in, const int* in_sizes, int n_in,
                              void* d_out, int out_size)
{
    const float* conv  = (const float*)d_in[0];
    const int4*  elems = (const int4*)d_in[1];
    const float4* inv  = (const float4*)d_in[2];
    float* out = (float*)d_out;

    int n_nodes = in_sizes[0] / 3;
    int E = in_sizes[1] / 4;
    int total_rows = 4 * E;

    pad_conv_kernel<<<(n_nodes + 127) / 128, 128>>>(conv, n_nodes);

    int rows_per_cta = 512;   // 2 tiles x 256
    int grid = (total_rows + rows_per_cta - 1) / rows_per_cta;
    fem_row_tma2_kernel<<<grid, 256>>>(elems, inv, out, total_rows);
}